// round 8
// baseline (speedup 1.0000x reference)
#include <cuda_runtime.h>
#include <cstdint>

#define E_  8
#define T_  2048
#define H_  2880
#define D_  2880
#define N2_ 5760

__device__ float g_xr[(size_t)T_ * H_];
__device__ float g_w1t[(size_t)E_ * N2_ * H_];
__device__ float g_w2t[(size_t)E_ * H_ * D_];
__device__ float g_hidden[(size_t)E_ * T_ * D_];

// ---------------- helpers ----------------
__device__ __forceinline__ unsigned smem_u32(const void* p) {
    return (unsigned)__cvta_generic_to_shared(p);
}
__device__ __forceinline__ void cp16(float* s, const float* g) {
    asm volatile("cp.async.cg.shared.global [%0], [%1], 16;" :: "r"(smem_u32(s)), "l"(g));
}
__device__ __forceinline__ void cp_commit() { asm volatile("cp.async.commit_group;"); }
__device__ __forceinline__ void cp_wait1()  { asm volatile("cp.async.wait_group 1;"); }
__device__ __forceinline__ void cp_wait0()  { asm volatile("cp.async.wait_group 0;"); }

__device__ __forceinline__ float tf32r(float x) {
    uint32_t r; asm("cvt.rna.tf32.f32 %0, %1;" : "=r"(r) : "f"(x));
    return __uint_as_float(r);
}
__device__ __forceinline__ void mma8(float* c, const uint32_t* a, const uint32_t* b) {
    asm volatile("mma.sync.aligned.m16n8k8.row.col.f32.tf32.tf32.f32 "
        "{%0,%1,%2,%3}, {%4,%5,%6,%7}, {%8,%9}, {%0,%1,%2,%3};"
        : "+f"(c[0]), "+f"(c[1]), "+f"(c[2]), "+f"(c[3])
        : "r"(a[0]), "r"(a[1]), "r"(a[2]), "r"(a[3]), "r"(b[0]), "r"(b[1]));
}
__device__ __forceinline__ void ldsm4(uint32_t& r0, uint32_t& r1, uint32_t& r2, uint32_t& r3,
                                      uint32_t addr) {
    asm volatile("ldmatrix.sync.aligned.m8n8.x4.shared.b16 {%0,%1,%2,%3}, [%4];"
        : "=r"(r0), "=r"(r1), "=r"(r2), "=r"(r3) : "r"(addr));
}
__device__ __forceinline__ void ldsm2(uint32_t& r0, uint32_t& r1, uint32_t addr) {
    asm volatile("ldmatrix.sync.aligned.m8n8.x2.shared.b16 {%0,%1}, [%2];"
        : "=r"(r0), "=r"(r1) : "r"(addr));
}

// ---------------- common ----------------
constexpr int BK = 32, NT = 256;
constexpr int A_FL = 128 * 32;              // 4096 floats per A stage

// GEMM1: 128x96 tile, 4 stages, pair barriers
constexpr int G1_BN = 96, G1_NF = 3, G1_WN = 24;
constexpr int G1_BFL = G1_BN * 32;          // 3072
constexpr int G1_STGF = A_FL + G1_BFL;      // 7168 floats (28 KB)
constexpr int G1_SMEM = 4 * G1_STGF * 4;    // 114688 B
constexpr int G1_GX = N2_ / G1_BN;          // 60
// GEMM2: 128x160 tile, 3 stages (R7 config)
constexpr int G2_BN = 160, G2_NF = 5, G2_WN = 40;
constexpr int G2_BFL = G2_BN * 32;          // 5120
constexpr int G2_STGF = A_FL + G2_BFL;      // 9216 floats (36 KB)
constexpr int G2_SMEM = 3 * G2_STGF * 4;    // 110592 B

// w2 transpose folded into gemm1 grid
constexpr int TP_TILES = (H_ / 32) * (D_ / 32) * E_;  // 64800
constexpr int TP_BLOCKS = 8 * 16 * 8;                 // 1024
constexpr int TP_PER_BLK = 64;

// swizzled loaders (rows x 32 floats; chunk' = chunk ^ (row&7))
template<int ROWS>
__device__ __forceinline__ void load_tile(float* S, const float* G, int lda, int tid) {
#pragma unroll
    for (int i = 0; i < ROWS * 8 / NT; i++) {
        int c = tid + i * NT;
        int r = c >> 3, q = c & 7;
        cp16(S + r * 32 + (q ^ (r & 7)) * 4, G + (size_t)r * lda + q * 4);
    }
}

// per-lane ldmatrix base offsets (bytes into stage)
__device__ __forceinline__ void offs_A(uint32_t (&aOff)[4], int wm, int lane) {
    const int rr = lane & 7, mm = lane >> 3;
#pragma unroll
    for (int i = 0; i < 4; i++) {
        const int row = wm * 64 + i * 16 + (mm & 1) * 8 + rr;
        aOff[i] = row * 128 + ((((mm >> 1) ^ (row & 7)) & 7) << 4);
    }
}
template<int WN, int NP>   // NP = number of x4 pair-loads
__device__ __forceinline__ void offs_B(uint32_t (&bOff)[NP + 1], int wn, int lane) {
    const int rr = lane & 7, mm = lane >> 3;
#pragma unroll
    for (int jp = 0; jp < NP; jp++) {
        const int row = wn * WN + (jp * 2 + (mm >> 1)) * 8 + rr;
        bOff[jp] = row * 128 + ((((mm & 1) ^ (row & 7)) & 7) << 4);
    }
    {
        const int row = wn * WN + NP * 16 + rr;
        bOff[NP] = row * 128 + ((((mm & 1) ^ (row & 7)) & 7) << 4);
    }
}

template<int NF, int NP>
__device__ __forceinline__ void compute_stage(uint32_t sA, uint32_t sB,
                                              const uint32_t (&aOff)[4],
                                              const uint32_t (&bOff)[NP + 1],
                                              float (&acc)[4][NF][4]) {
#pragma unroll
    for (int ks = 0; ks < 4; ks++) {
        const uint32_t kx = ks * 32;
        uint32_t a[4][4], b[NF][2];
#pragma unroll
        for (int i = 0; i < 4; i++)
            ldsm4(a[i][0], a[i][1], a[i][2], a[i][3], sA + (aOff[i] ^ kx));
#pragma unroll
        for (int jp = 0; jp < NP; jp++)
            ldsm4(b[2 * jp][0], b[2 * jp][1], b[2 * jp + 1][0], b[2 * jp + 1][1],
                  sB + (bOff[jp] ^ kx));
        ldsm2(b[NF - 1][0], b[NF - 1][1], sB + (bOff[NP] ^ kx));
#pragma unroll
        for (int i = 0; i < 4; i++)
#pragma unroll
            for (int j = 0; j < NF; j++)
                mma8(acc[i][j], a[i], b[j]);
    }
}

// ================= preprocess =================
__global__ void k_round4(const float4* __restrict__ in, float4* __restrict__ out, size_t n4) {
    size_t i = (size_t)blockIdx.x * blockDim.x + threadIdx.x;
    size_t st = (size_t)gridDim.x * blockDim.x;
    for (; i < n4; i += st) {
        float4 v = in[i];
        v.x = tf32r(v.x); v.y = tf32r(v.y); v.z = tf32r(v.z); v.w = tf32r(v.w);
        out[i] = v;
    }
}
__global__ void k_transpose(const float* __restrict__ in, float* __restrict__ out, int R, int C) {
    __shared__ float t[32][33];
    const float* iz = in + (size_t)blockIdx.z * R * C;
    float* oz = out + (size_t)blockIdx.z * R * C;
    int c0 = blockIdx.x * 32, r0 = blockIdx.y * 32;
#pragma unroll
    for (int i = 0; i < 32; i += 8)
        t[threadIdx.y + i][threadIdx.x] = iz[(size_t)(r0 + threadIdx.y + i) * C + c0 + threadIdx.x];
    __syncthreads();
#pragma unroll
    for (int i = 0; i < 32; i += 8)
        oz[(size_t)(c0 + threadIdx.y + i) * R + r0 + threadIdx.x] = tf32r(t[threadIdx.x][threadIdx.y + i]);
}

// ================= GEMM1 (+ fused w2 transpose blocks) =================
__global__ void __launch_bounds__(NT, 2)
k_gemm1(const float* __restrict__ b1, const float* __restrict__ routing,
        const float* __restrict__ w2) {
    extern __shared__ __align__(128) float sm[];
    const int tid = threadIdx.x;

    if (blockIdx.x >= G1_GX) {
        // ---- w2 transpose role: [E][D][H] -> g_w2t [E][H][D], tf32-rounded ----
        const int bidx = (blockIdx.x - G1_GX) + 8 * (blockIdx.y + 16 * blockIdx.z);
        float (*t33)[33] = (float (*)[33])sm;
        const int tx = tid & 31, tw = tid >> 5;
        const int base = bidx * TP_PER_BLK;
        for (int tt = base; tt < base + TP_PER_BLK && tt < TP_TILES; tt++) {
            const int e = tt / 8100, rem = tt % 8100;
            const int cx = rem / 90, ry = rem % 90;
            const int c0 = cx * 32, r0 = ry * 32;
            const float* iz = w2 + (size_t)e * D_ * H_;
            float* oz = g_w2t + (size_t)e * H_ * D_;
#pragma unroll
            for (int i = 0; i < 32; i += 8)
                t33[tw + i][tx] = iz[(size_t)(r0 + tw + i) * H_ + c0 + tx];
            __syncthreads();
#pragma unroll
            for (int i = 0; i < 32; i += 8)
                oz[(size_t)(c0 + tw + i) * D_ + r0 + tx] = tf32r(t33[tx][tw + i]);
            __syncthreads();
        }
        return;
    }

    // ---- GEMM role ----
    const int lane = tid & 31, warp = tid >> 5;
    const int wm = warp & 1, wn = warp >> 1;
    const int n0 = blockIdx.x * G1_BN;
    const int t0 = blockIdx.y * 128;
    const int e  = blockIdx.z;

    const uint32_t sb = smem_u32(sm);
    const float* Ag = g_xr + (size_t)t0 * H_;
    const float* Bg = g_w1t + ((size_t)e * N2_ + n0) * H_;

    uint32_t aOff[4], bOff[2];
    offs_A(aOff, wm, lane);
    offs_B<G1_WN, 1>(bOff, wn, lane);

    float acc[4][G1_NF][4];
#pragma unroll
    for (int i = 0; i < 4; i++)
#pragma unroll
        for (int j = 0; j < G1_NF; j++)
#pragma unroll
            for (int q = 0; q < 4; q++) acc[i][j][q] = 0.f;

    constexpr int KT = H_ / BK;     // 90
    constexpr int NPAIR = KT / 2;   // 45

    // preamble: pair 0 -> slots {0,1}, one commit group
    load_tile<128>(sm, Ag, H_, tid);
    load_tile<G1_BN>(sm + A_FL, Bg, H_, tid);
    load_tile<128>(sm + G1_STGF, Ag + BK, H_, tid);
    load_tile<G1_BN>(sm + G1_STGF + A_FL, Bg + BK, H_, tid);
    cp_commit();

    for (int kp = 0; kp < NPAIR; kp++) {
        cp_wait0();
        __syncthreads();
        const int nk = 2 * kp + 2;
        if (nk < KT) {
            const int sl = (kp & 1) ? 0 : 2;   // other stage pair
            load_tile<128>(sm + sl * G1_STGF, Ag + nk * BK, H_, tid);
            load_tile<G1_BN>(sm + sl * G1_STGF + A_FL, Bg + nk * BK, H_, tid);
            load_tile<128>(sm + (sl + 1) * G1_STGF, Ag + (nk + 1) * BK, H_, tid);
            load_tile<G1_BN>(sm + (sl + 1) * G1_STGF + A_FL, Bg + (nk + 1) * BK, H_, tid);
            cp_commit();
        }
        const int s0 = (kp & 1) ? 2 : 0;
        compute_stage<G1_NF, 1>(sb + s0 * G1_STGF * 4, sb + (s0 * G1_STGF + A_FL) * 4,
                                aOff, bOff, acc);
        compute_stage<G1_NF, 1>(sb + (s0 + 1) * G1_STGF * 4, sb + ((s0 + 1) * G1_STGF + A_FL) * 4,
                                aOff, bOff, acc);
    }

    __syncthreads();
    if (tid < G1_BN) sm[tid] = b1[(size_t)e * N2_ + n0 + tid];
    __syncthreads();

    const int ra = lane >> 2, ca2 = 2 * (lane & 3);
#pragma unroll
    for (int i = 0; i < 4; i++)
#pragma unroll
        for (int h = 0; h < 2; h++) {
            const int row = wm * 64 + i * 16 + h * 8 + ra;
            const float rw = routing[(size_t)(t0 + row) * E_ + e];
            float* gh = g_hidden + ((size_t)e * T_ + t0 + row) * D_ + (n0 >> 1);
#pragma unroll
            for (int j = 0; j < G1_NF; j++) {
                const int C = wn * G1_WN + j * 8 + ca2;
                float gate = acc[i][j][2 * h]     + sm[C];
                float up   = acc[i][j][2 * h + 1] + sm[C + 1];
                gate = fminf(gate, 7.0f);
                up   = fminf(fmaxf(up, -7.0f), 7.0f);
                const float glu = gate / (1.0f + __expf(-1.702f * gate));
                gh[C >> 1] = tf32r((up + 1.0f) * glu * rw);
            }
        }
}

// ================= GEMM2 (R7 config, unchanged) =================
__global__ void __launch_bounds__(NT, 2)
k_gemm2(const float* __restrict__ b2, const float* __restrict__ routing,
        float* __restrict__ out) {
    extern __shared__ __align__(128) float sm[];
    const int tid = threadIdx.x, lane = tid & 31, warp = tid >> 5;
    const int wm = warp & 1, wn = warp >> 1;
    const int h0 = blockIdx.x * G2_BN;
    const int t0 = blockIdx.y * 128;

    const uint32_t sb = smem_u32(sm);
    uint32_t aOff[4], bOff[3];
    offs_A(aOff, wm, lane);
    offs_B<G2_WN, 2>(bOff, wn, lane);

    float acc[4][G2_NF][4];
#pragma unroll
    for (int i = 0; i < 4; i++)
#pragma unroll
        for (int j = 0; j < G2_NF; j++)
#pragma unroll
            for (int q = 0; q < 4; q++) acc[i][j][q] = 0.f;

    constexpr int KPE = D_ / BK;   // 90
    constexpr int KT  = E_ * KPE;  // 720

#pragma unroll
    for (int s = 0; s < 2; s++) {
        load_tile<128>(sm + s * G2_STGF, g_hidden + (size_t)t0 * D_ + s * BK, D_, tid);
        load_tile<G2_BN>(sm + s * G2_STGF + A_FL, g_w2t + (size_t)h0 * D_ + s * BK, D_, tid);
        cp_commit();
    }

    int ez = 0, kk = 2;
    for (int kt = 0; kt < KT; kt++) {
        if (kt < KT - 1) cp_wait1(); else cp_wait0();
        __syncthreads();
        const int nk = kt + 2;
        if (nk < KT) {
            const int ns = nk % 3;
            load_tile<128>(sm + ns * G2_STGF, g_hidden + ((size_t)ez * T_ + t0) * D_ + kk * BK, D_, tid);
            load_tile<G2_BN>(sm + ns * G2_STGF + A_FL, g_w2t + ((size_t)ez * H_ + h0) * D_ + kk * BK, D_, tid);
            cp_commit();
            if (++kk == KPE) { kk = 0; ez++; }
        }
        const int s = kt % 3;
        compute_stage<G2_NF, 2>(sb + s * G2_STGF * 4, sb + (s * G2_STGF + A_FL) * 4,
                                aOff, bOff, acc);
    }

    __syncthreads();
    for (int i = tid; i < E_ * G2_BN; i += NT) {
        const int ee = i / G2_BN, c = i - ee * G2_BN;
        sm[i] = b2[(size_t)ee * H_ + h0 + c];
    }
    __syncthreads();

    const int ra = lane >> 2, ca2 = 2 * (lane & 3);
#pragma unroll
    for (int i = 0; i < 4; i++)
#pragma unroll
        for (int h = 0; h < 2; h++) {
            const int t = t0 + wm * 64 + i * 16 + h * 8 + ra;
            const float4 r03 = ((const float4*)routing)[(size_t)t * 2];
            const float4 r47 = ((const float4*)routing)[(size_t)t * 2 + 1];
            const float rwv[8] = { r03.x, r03.y, r03.z, r03.w, r47.x, r47.y, r47.z, r47.w };
            float* orow = out + (size_t)t * H_ + h0;
#pragma unroll
            for (int j = 0; j < G2_NF; j++) {
                const int C = wn * G2_WN + j * 8 + ca2;
                float v0 = acc[i][j][2 * h];
                float v1 = acc[i][j][2 * h + 1];
#pragma unroll
                for (int ee = 0; ee < E_; ee++) {
                    v0 += rwv[ee] * sm[ee * G2_BN + C];
                    v1 += rwv[ee] * sm[ee * G2_BN + C + 1];
                }
                *(float2*)(orow + C) = make_float2(v0, v1);
            }
        }
}

// ================= host ====================
extern "C" void kernel_launch(void* const* d_in, const int* in_sizes, int n_in,
                              void* d_out, int out_size) {
    const float *x = nullptr, *rw = nullptr, *w1 = nullptr, *b1 = nullptr,
                *w2 = nullptr, *b2 = nullptr;
    for (int i = 0; i < n_in; i++) {
        const long long s = in_sizes[i];
        const float* p = (const float*)d_in[i];
        if      (s == (long long)T_ * H_)        x  = p;
        else if (s == (long long)T_ * E_)        rw = p;
        else if (s == (long long)E_ * H_ * N2_)  w1 = p;
        else if (s == (long long)E_ * N2_)       b1 = p;
        else if (s == (long long)E_ * D_ * H_)   w2 = p;
        else if (s == (long long)E_ * H_)        b2 = p;
    }
    float* out = (float*)d_out;

    void *p_xr, *p_w1t;
    cudaGetSymbolAddress(&p_xr,  g_xr);
    cudaGetSymbolAddress(&p_w1t, g_w1t);

    cudaFuncSetAttribute(k_gemm1, cudaFuncAttributeMaxDynamicSharedMemorySize, G1_SMEM);
    cudaFuncSetAttribute(k_gemm2, cudaFuncAttributeMaxDynamicSharedMemorySize, G2_SMEM);

    k_round4<<<4096, 256>>>((const float4*)x, (float4*)p_xr, (size_t)T_ * H_ / 4);
    dim3 tb(32, 8);
    k_transpose<<<dim3(N2_ / 32, H_ / 32, E_), tb>>>(w1, (float*)p_w1t, H_, N2_);

    // gemm1 grid: x<60 GEMM blocks, x>=60 w2-transpose blocks (overlapped)
    k_gemm1<<<dim3(G1_GX + 8, T_ / 128, E_), NT, G1_SMEM>>>(b1, rw, w2);
    k_gemm2<<<dim3(H_ / G2_BN, T_ / 128), NT, G2_SMEM>>>(b2, rw, out);
}

// round 9
// speedup vs baseline: 1.9265x; 1.9265x over previous
#include <cuda_runtime.h>
#include <cuda_fp16.h>
#include <cstdint>

#define E_  8
#define T_  2048
#define H_  2880
#define D_  2880
#define N2_ 5760

// fp16 scratch: x, K-major weights, intermediate hidden
__device__ __half g_xh[(size_t)T_ * H_];                 // [T][H]
__device__ __half g_w1t[(size_t)E_ * N2_ * H_];          // [E][N2][H]
__device__ __half g_w2t[(size_t)E_ * H_ * D_];           // [E][H][D]
__device__ __half g_hidden[(size_t)E_ * T_ * D_];        // [E][T][D]

// ---------------- helpers ----------------
__device__ __forceinline__ unsigned smem_u32(const void* p) {
    return (unsigned)__cvta_generic_to_shared(p);
}
__device__ __forceinline__ void cp16h(__half* s, const __half* g) {
    asm volatile("cp.async.cg.shared.global [%0], [%1], 16;" :: "r"(smem_u32(s)), "l"(g));
}
__device__ __forceinline__ void cp_commit() { asm volatile("cp.async.commit_group;"); }
__device__ __forceinline__ void cp_wait1()  { asm volatile("cp.async.wait_group 1;"); }
__device__ __forceinline__ void cp_wait0()  { asm volatile("cp.async.wait_group 0;"); }

__device__ __forceinline__ void mma16(float* c, const uint32_t* a, const uint32_t* b) {
    asm volatile("mma.sync.aligned.m16n8k16.row.col.f32.f16.f16.f32 "
        "{%0,%1,%2,%3}, {%4,%5,%6,%7}, {%8,%9}, {%0,%1,%2,%3};"
        : "+f"(c[0]), "+f"(c[1]), "+f"(c[2]), "+f"(c[3])
        : "r"(a[0]), "r"(a[1]), "r"(a[2]), "r"(a[3]), "r"(b[0]), "r"(b[1]));
}
__device__ __forceinline__ void ldsm4(uint32_t& r0, uint32_t& r1, uint32_t& r2, uint32_t& r3,
                                      uint32_t addr) {
    asm volatile("ldmatrix.sync.aligned.m8n8.x4.shared.b16 {%0,%1,%2,%3}, [%4];"
        : "=r"(r0), "=r"(r1), "=r"(r2), "=r"(r3) : "r"(addr));
}
__device__ __forceinline__ void ldsm2(uint32_t& r0, uint32_t& r1, uint32_t addr) {
    asm volatile("ldmatrix.sync.aligned.m8n8.x2.shared.b16 {%0,%1}, [%2];"
        : "=r"(r0), "=r"(r1) : "r"(addr));
}

// ---------------- tiling ----------------
// rows of 64 halves = 128 bytes, 8 x 16B chunks; BK = 64 halves per stage
constexpr int BM = 128, BN = 160, BK = 64;
constexpr int NT = 256;                        // 8 warps: wm = warp&1, wn = warp>>1
constexpr int WN = 40, NF = 5;
constexpr int A_BYTES = BM * 128;              // 16384
constexpr int B_BYTES = BN * 128;              // 20480
constexpr int STG_B = A_BYTES + B_BYTES;       // 36864
constexpr int STAGES = 3;
constexpr int SMEM_B = STAGES * STG_B;         // 110592 -> 2 CTAs/SM

// swizzled tile load: ROWS x 64 halves; chunk' = chunk ^ (row&7)
template<int ROWS>
__device__ __forceinline__ void load_tile(__half* S, const __half* G, int lda, int tid) {
#pragma unroll
    for (int i = 0; i < ROWS * 8 / NT; i++) {
        int c = tid + i * NT;
        int r = c >> 3, q = c & 7;
        cp16h(S + r * 64 + ((q ^ (r & 7)) << 3), G + (size_t)r * lda + q * 8);
    }
}

// per-lane ldmatrix base offsets (bytes into stage region)
__device__ __forceinline__ void offs_A(uint32_t (&aOff)[4], int wm, int lane) {
    const int rr = lane & 7, mm = lane >> 3;
#pragma unroll
    for (int i = 0; i < 4; i++) {
        const int row = wm * 64 + i * 16 + (mm & 1) * 8 + rr;     // bit0 -> +8 m-rows
        aOff[i] = row * 128 + ((((mm >> 1) ^ (row & 7)) & 7) << 4); // bit1 -> k+8 (chunk+1)
    }
}
__device__ __forceinline__ void offs_B(uint32_t (&bOff)[3], int wn, int lane) {
    const int rr = lane & 7, mm = lane >> 3;
#pragma unroll
    for (int jp = 0; jp < 2; jp++) {
        const int row = wn * WN + (jp * 2 + (mm >> 1)) * 8 + rr;  // bit1 -> +8 n-rows
        bOff[jp] = row * 128 + ((((mm & 1) ^ (row & 7)) & 7) << 4); // bit0 -> k+8
    }
    {
        const int row = wn * WN + 32 + rr;
        bOff[2] = row * 128 + ((((mm & 1) ^ (row & 7)) & 7) << 4);
    }
}

// one stage = BK=64 halves = 4 k-steps of 16
__device__ __forceinline__ void compute_stage(uint32_t sA, uint32_t sB,
                                              const uint32_t (&aOff)[4],
                                              const uint32_t (&bOff)[3],
                                              float (&acc)[4][NF][4]) {
#pragma unroll
    for (int ks = 0; ks < 4; ks++) {
        const uint32_t kx = ks * 32;          // 2 chunks (32B) per k16 step
        uint32_t a[4][4], b[NF][2];
#pragma unroll
        for (int i = 0; i < 4; i++)
            ldsm4(a[i][0], a[i][1], a[i][2], a[i][3], sA + (aOff[i] ^ kx));
        ldsm4(b[0][0], b[0][1], b[1][0], b[1][1], sB + (bOff[0] ^ kx));
        ldsm4(b[2][0], b[2][1], b[3][0], b[3][1], sB + (bOff[1] ^ kx));
        ldsm2(b[4][0], b[4][1], sB + (bOff[2] ^ kx));
#pragma unroll
        for (int i = 0; i < 4; i++)
#pragma unroll
            for (int j = 0; j < NF; j++)
                mma16(acc[i][j], a[i], b[j]);
    }
}

// ================= preprocess =================
__global__ void k_tohalf(const float2* __restrict__ in, __half2* __restrict__ out, size_t n2) {
    size_t i = (size_t)blockIdx.x * blockDim.x + threadIdx.x;
    size_t st = (size_t)gridDim.x * blockDim.x;
    for (; i < n2; i += st) {
        float2 v = in[i];
        out[i] = __floats2half2_rn(v.x, v.y);
    }
}
// [z][R][C] fp32 -> [z][C][R] fp16
__global__ void k_transpose_h(const float* __restrict__ in, __half* __restrict__ out, int R, int C) {
    __shared__ float t[32][33];
    const float* iz = in + (size_t)blockIdx.z * R * C;
    __half* oz = out + (size_t)blockIdx.z * R * C;
    int c0 = blockIdx.x * 32, r0 = blockIdx.y * 32;
#pragma unroll
    for (int i = 0; i < 32; i += 8)
        t[threadIdx.y + i][threadIdx.x] = iz[(size_t)(r0 + threadIdx.y + i) * C + c0 + threadIdx.x];
    __syncthreads();
#pragma unroll
    for (int i = 0; i < 32; i += 8)
        oz[(size_t)(c0 + threadIdx.y + i) * R + r0 + threadIdx.x] = __float2half_rn(t[threadIdx.x][threadIdx.y + i]);
}

// ================= GEMM1: x @ w1t^T + b1 -> GLU -> routing -> g_hidden ======
__global__ void __launch_bounds__(NT, 2)
k_gemm1(const float* __restrict__ b1, const float* __restrict__ routing) {
    extern __shared__ __align__(128) char smc[];
    __half* smh = (__half*)smc;
    float* smf = (float*)smc;
    const int tid = threadIdx.x, lane = tid & 31, warp = tid >> 5;
    const int wm = warp & 1, wn = warp >> 1;
    const int n0 = blockIdx.x * BN;
    const int t0 = blockIdx.y * BM;
    const int e  = blockIdx.z;

    const uint32_t sb = smem_u32(smc);
    const __half* Ag = g_xh + (size_t)t0 * H_;
    const __half* Bg = g_w1t + ((size_t)e * N2_ + n0) * H_;

    uint32_t aOff[4], bOff[3];
    offs_A(aOff, wm, lane);
    offs_B(bOff, wn, lane);

    float acc[4][NF][4];
#pragma unroll
    for (int i = 0; i < 4; i++)
#pragma unroll
        for (int j = 0; j < NF; j++)
#pragma unroll
            for (int q = 0; q < 4; q++) acc[i][j][q] = 0.f;

    constexpr int KT = H_ / BK;   // 45
#pragma unroll
    for (int s = 0; s < 2; s++) {
        load_tile<BM>(smh + s * STG_B / 2, Ag + s * BK, H_, tid);
        load_tile<BN>(smh + (s * STG_B + A_BYTES) / 2, Bg + s * BK, H_, tid);
        cp_commit();
    }

    for (int kt = 0; kt < KT; kt++) {
        if (kt < KT - 1) cp_wait1(); else cp_wait0();
        __syncthreads();
        const int nk = kt + 2;
        if (nk < KT) {
            const int ns = nk % 3;
            load_tile<BM>(smh + ns * STG_B / 2, Ag + nk * BK, H_, tid);
            load_tile<BN>(smh + (ns * STG_B + A_BYTES) / 2, Bg + nk * BK, H_, tid);
            cp_commit();
        }
        const int s = kt % 3;
        compute_stage(sb + s * STG_B, sb + s * STG_B + A_BYTES, aOff, bOff, acc);
    }

    __syncthreads();
    if (tid < BN) smf[tid] = b1[(size_t)e * N2_ + n0 + tid];
    __syncthreads();

    const int ra = lane >> 2, ca2 = 2 * (lane & 3);
#pragma unroll
    for (int i = 0; i < 4; i++)
#pragma unroll
        for (int h = 0; h < 2; h++) {
            const int row = wm * 64 + i * 16 + h * 8 + ra;
            const float rw = routing[(size_t)(t0 + row) * E_ + e];
            __half* gh = g_hidden + ((size_t)e * T_ + t0 + row) * D_ + (n0 >> 1);
#pragma unroll
            for (int j = 0; j < NF; j++) {
                const int C = wn * WN + j * 8 + ca2;
                float gate = acc[i][j][2 * h]     + smf[C];
                float up   = acc[i][j][2 * h + 1] + smf[C + 1];
                gate = fminf(gate, 7.0f);
                up   = fminf(fmaxf(up, -7.0f), 7.0f);
                const float glu = gate / (1.0f + __expf(-1.702f * gate));
                gh[C >> 1] = __float2half_rn((up + 1.0f) * glu * rw);
            }
        }
}

// ================= GEMM2: hidden @ w2t^T (flat K over e,d) + routed bias ====
__global__ void __launch_bounds__(NT, 2)
k_gemm2(const float* __restrict__ b2, const float* __restrict__ routing,
        float* __restrict__ out) {
    extern __shared__ __align__(128) char smc[];
    __half* smh = (__half*)smc;
    float* smf = (float*)smc;
    const int tid = threadIdx.x, lane = tid & 31, warp = tid >> 5;
    const int wm = warp & 1, wn = warp >> 1;
    const int h0 = blockIdx.x * BN;
    const int t0 = blockIdx.y * BM;

    const uint32_t sb = smem_u32(smc);
    uint32_t aOff[4], bOff[3];
    offs_A(aOff, wm, lane);
    offs_B(bOff, wn, lane);

    float acc[4][NF][4];
#pragma unroll
    for (int i = 0; i < 4; i++)
#pragma unroll
        for (int j = 0; j < NF; j++)
#pragma unroll
            for (int q = 0; q < 4; q++) acc[i][j][q] = 0.f;

    constexpr int KPE = D_ / BK;   // 45
    constexpr int KT  = E_ * KPE;  // 360

#pragma unroll
    for (int s = 0; s < 2; s++) {
        load_tile<BM>(smh + s * STG_B / 2, g_hidden + (size_t)t0 * D_ + s * BK, D_, tid);
        load_tile<BN>(smh + (s * STG_B + A_BYTES) / 2, g_w2t + (size_t)h0 * D_ + s * BK, D_, tid);
        cp_commit();
    }

    int ez = 0, kk = 2;
    for (int kt = 0; kt < KT; kt++) {
        if (kt < KT - 1) cp_wait1(); else cp_wait0();
        __syncthreads();
        const int nk = kt + 2;
        if (nk < KT) {
            const int ns = nk % 3;
            load_tile<BM>(smh + ns * STG_B / 2,
                          g_hidden + ((size_t)ez * T_ + t0) * D_ + kk * BK, D_, tid);
            load_tile<BN>(smh + (ns * STG_B + A_BYTES) / 2,
                          g_w2t + ((size_t)ez * H_ + h0) * D_ + kk * BK, D_, tid);
            cp_commit();
            if (++kk == KPE) { kk = 0; ez++; }
        }
        const int s = kt % 3;
        compute_stage(sb + s * STG_B, sb + s * STG_B + A_BYTES, aOff, bOff, acc);
    }

    __syncthreads();
    for (int i = tid; i < E_ * BN; i += NT) {
        const int ee = i / BN, c = i - ee * BN;
        smf[i] = b2[(size_t)ee * H_ + h0 + c];
    }
    __syncthreads();

    const int ra = lane >> 2, ca2 = 2 * (lane & 3);
#pragma unroll
    for (int i = 0; i < 4; i++)
#pragma unroll
        for (int h = 0; h < 2; h++) {
            const int t = t0 + wm * 64 + i * 16 + h * 8 + ra;
            const float4 r03 = ((const float4*)routing)[(size_t)t * 2];
            const float4 r47 = ((const float4*)routing)[(size_t)t * 2 + 1];
            const float rwv[8] = { r03.x, r03.y, r03.z, r03.w, r47.x, r47.y, r47.z, r47.w };
            float* orow = out + (size_t)t * H_ + h0;
#pragma unroll
            for (int j = 0; j < NF; j++) {
                const int C = wn * WN + j * 8 + ca2;
                float v0 = acc[i][j][2 * h];
                float v1 = acc[i][j][2 * h + 1];
#pragma unroll
                for (int ee = 0; ee < E_; ee++) {
                    v0 += rwv[ee] * smf[ee * BN + C];
                    v1 += rwv[ee] * smf[ee * BN + C + 1];
                }
                *(float2*)(orow + C) = make_float2(v0, v1);
            }
        }
}

// ================= host ====================
extern "C" void kernel_launch(void* const* d_in, const int* in_sizes, int n_in,
                              void* d_out, int out_size) {
    const float *x = nullptr, *rw = nullptr, *w1 = nullptr, *b1 = nullptr,
                *w2 = nullptr, *b2 = nullptr;
    for (int i = 0; i < n_in; i++) {
        const long long s = in_sizes[i];
        const float* p = (const float*)d_in[i];
        if      (s == (long long)T_ * H_)        x  = p;
        else if (s == (long long)T_ * E_)        rw = p;
        else if (s == (long long)E_ * H_ * N2_)  w1 = p;
        else if (s == (long long)E_ * N2_)       b1 = p;
        else if (s == (long long)E_ * D_ * H_)   w2 = p;
        else if (s == (long long)E_ * H_)        b2 = p;
    }
    float* out = (float*)d_out;

    void *p_xh, *p_w1t, *p_w2t;
    cudaGetSymbolAddress(&p_xh,  g_xh);
    cudaGetSymbolAddress(&p_w1t, g_w1t);
    cudaGetSymbolAddress(&p_w2t, g_w2t);

    cudaFuncSetAttribute(k_gemm1, cudaFuncAttributeMaxDynamicSharedMemorySize, SMEM_B);
    cudaFuncSetAttribute(k_gemm2, cudaFuncAttributeMaxDynamicSharedMemorySize, SMEM_B);

    k_tohalf<<<4096, 256>>>((const float2*)x, (__half2*)p_xh, (size_t)T_ * H_ / 2);
    dim3 tb(32, 8);
    k_transpose_h<<<dim3(N2_ / 32, H_ / 32, E_), tb>>>(w1, (__half*)p_w1t, H_, N2_);
    k_transpose_h<<<dim3(H_ / 32, D_ / 32, E_), tb>>>(w2, (__half*)p_w2t, D_, H_);

    k_gemm1<<<dim3(N2_ / BN, T_ / BM, E_), NT, SMEM_B>>>(b1, rw);
    k_gemm2<<<dim3(H_ / BN, T_ / BM), NT, SMEM_B>>>(b2, rw, out);
}